// round 13
// baseline (speedup 1.0000x reference)
#include <cuda_runtime.h>
#include <cuda_fp16.h>
#include <cstdint>
#include <math.h>

#define BATCH  2
#define S_LEN  2048
#define HID_D  2048
#define NH     16
#define NKV    2
#define HD     128
#define QKV_N  ((NH + 2*NKV) * HD)   // 2560
#define NTOK   (BATCH * S_LEN)       // 4096
#define OUT_N  (NH * HD)             // 2048
#define SCALE  0.08838834764831843f  // 128^-0.5

// ---------------- scratch (device globals; no allocation allowed) ----------------
__device__ __align__(16) float  g_cs[(size_t)S_LEN * HD];
__device__ __align__(16) __half g_hidden_h[(size_t)NTOK * HID_D];
__device__ __align__(16) __half g_wqkvT_h[(size_t)QKV_N * HID_D];
__device__ __align__(16) __half g_woT_h[(size_t)HID_D * OUT_N];
__device__ __align__(16) __half g_attnh[(size_t)NTOK * OUT_N];
__device__ __align__(16) __half g_qh[(size_t)BATCH * NH * S_LEN * HD];   // roped+scaled Q
__device__ __align__(16) __half g_kh[(size_t)BATCH * NKV * S_LEN * HD];  // roped K
__device__ __align__(16) __half g_vh[(size_t)BATCH * NKV * S_LEN * HD];  // V

// ---------------- common PTX helpers ----------------
__device__ __forceinline__ uint32_t smem_u32(const void* p) {
    uint32_t a;
    asm("{ .reg .u64 t; cvta.to.shared.u64 t, %1; cvt.u32.u64 %0, t; }" : "=r"(a) : "l"(p));
    return a;
}
#define CP16(d, s) \
    asm volatile("cp.async.cg.shared.global [%0], [%1], 16;" :: "r"(d), "l"(s))
#define CP_COMMIT() asm volatile("cp.async.commit_group;" ::: "memory")
#define LDSM4(r0, r1, r2, r3, a)                                              \
    asm volatile("ldmatrix.sync.aligned.m8n8.x4.shared.b16 {%0,%1,%2,%3}, [%4];" \
                 : "=r"(r0), "=r"(r1), "=r"(r2), "=r"(r3) : "r"(a))
#define LDSM4T(r0, r1, r2, r3, a)                                             \
    asm volatile("ldmatrix.sync.aligned.m8n8.x4.trans.shared.b16 {%0,%1,%2,%3}, [%4];" \
                 : "=r"(r0), "=r"(r1), "=r"(r2), "=r"(r3) : "r"(a))
#define MMA_F16(d, a, b)                                                      \
    asm volatile("mma.sync.aligned.m16n8k16.row.col.f32.f16.f16.f32 "         \
                 "{%0,%1,%2,%3}, {%4,%5,%6,%7}, {%8,%9}, {%0,%1,%2,%3};"      \
                 : "+f"(d[0]), "+f"(d[1]), "+f"(d[2]), "+f"(d[3])             \
                 : "r"(a[0]), "r"(a[1]), "r"(a[2]), "r"(a[3]),                \
                   "r"(b[0]), "r"(b[1]))

// ---------------- RoPE cos/sin table (fp64 for angle accuracy) ----------------
__global__ void rope_table_kernel() {
    int idx = blockIdx.x * blockDim.x + threadIdx.x;
    if (idx >= S_LEN * 64) return;
    int s = idx >> 6, i = idx & 63;
    double inv = pow(1000000.0, -(double)i / 64.0);
    double ang = (double)s * inv;
    g_cs[s * HD + i]      = (float)cos(ang);
    g_cs[s * HD + 64 + i] = (float)sin(ang);
}

// ---------------- fp32 -> fp16 convert ----------------
__global__ void f2h_kernel(const float* __restrict__ in, __half* __restrict__ out, int n4) {
    int i = blockIdx.x * blockDim.x + threadIdx.x;
    if (i >= n4) return;
    float4 v = ((const float4*)in)[i];
    __half2 h0 = __floats2half2_rn(v.x, v.y);
    __half2 h1 = __floats2half2_rn(v.z, v.w);
    ((uint2*)out)[i] = make_uint2(*(unsigned*)&h0, *(unsigned*)&h1);
}

// ---------------- weight transpose + convert: out_h[N][K] = in[K][N] ----------------
__global__ void transpose_h_kernel(const float* __restrict__ in, __half* __restrict__ out,
                                   int rows, int cols) {
    __shared__ float t[32][33];
    int x = blockIdx.x * 32 + threadIdx.x;
    int y = blockIdx.y * 32 + threadIdx.y;
#pragma unroll
    for (int j = 0; j < 32; j += 8)
        t[threadIdx.y + j][threadIdx.x] = in[(size_t)(y + j) * cols + x];
    __syncthreads();
    x = blockIdx.y * 32 + threadIdx.x;
    y = blockIdx.x * 32 + threadIdx.y;
#pragma unroll
    for (int j = 0; j < 32; j += 8)
        out[(size_t)(y + j) * rows + x] = __float2half(t[threadIdx.x][threadIdx.y + j]);
}

// ============ fp16 mma GEMM core (cp.async 4-stage + ldmatrix) ============
#define GSTAGE  16384
#define GSMEM   (4 * GSTAGE)
#define QSMEM   (132 * 128 * 4)      // 67584: rope-epilogue staging (>= GSMEM)

// mainloop shared by both GEMMs; acc indexed [mt][nt][r]
#define GEMM_MAINLOOP(A_, Bt_, K_)                                            \
    const int fr = tid >> 1;                                                  \
    const int fc0 = (tid & 1) * 2;                                            \
    const __half* Ap = (A_)  + (size_t)(bm + fr) * (K_) + fc0 * 8;            \
    const __half* Bp = (Bt_) + (size_t)(bn + fr) * (K_) + fc0 * 8;            \
    const uint32_t fsw0 = (uint32_t)(fr * 64 + (((fc0 + 0) ^ ((fr >> 1) & 3)) << 4)); \
    const uint32_t fsw1 = (uint32_t)(fr * 64 + (((fc0 + 1) ^ ((fr >> 1) & 3)) << 4)); \
    uint32_t a_off[4][2], b_off[2][2];                                        \
    {                                                                         \
        const int j = lane >> 3, lr = lane & 7;                               \
        for (int mt = 0; mt < 4; mt++)                                        \
            for (int ks = 0; ks < 2; ks++) {                                  \
                int row = wm + mt * 16 + (j & 1) * 8 + lr;                    \
                int kc  = ks * 2 + (j >> 1);                                  \
                a_off[mt][ks] = (uint32_t)(row * 64 + ((kc ^ ((row >> 1) & 3)) << 4)); \
            }                                                                 \
        for (int np = 0; np < 2; np++)                                        \
            for (int ks = 0; ks < 2; ks++) {                                  \
                int nt  = np * 2 + (j >> 1);                                  \
                int row = wn + nt * 8 + lr;                                   \
                int kc  = ks * 2 + (j & 1);                                   \
                b_off[np][ks] = (uint32_t)(8192 + row * 64 + ((kc ^ ((row >> 1) & 3)) << 4)); \
            }                                                                 \
    }                                                                         \
    float acc[4][4][4];                                                       \
    for (int mt = 0; mt < 4; mt++)                                            \
        for (int nt = 0; nt < 4; nt++)                                        \
            for (int r = 0; r < 4; r++) acc[mt][nt][r] = 0.0f;                \
    const int nk = (K_) >> 5;                                                 \
    auto load_stage = [&](int kt, int st) {                                   \
        uint32_t s = sb + st * GSTAGE;                                        \
        const __half* ap = Ap + kt * 32;                                      \
        const __half* bp = Bp + kt * 32;                                      \
        CP16(s + fsw0,        ap);                                            \
        CP16(s + fsw1,        ap + 8);                                        \
        CP16(s + 8192 + fsw0, bp);                                            \
        CP16(s + 8192 + fsw1, bp + 8);                                        \
    };                                                                        \
    for (int s = 0; s < 3; s++) { load_stage(s, s); CP_COMMIT(); }            \
    for (int kt = 0; kt < nk; kt++) {                                         \
        asm volatile("cp.async.wait_group 2;" ::: "memory");                  \
        __syncthreads();                                                      \
        const int st = kt & 3;                                                \
        if (kt + 3 < nk) load_stage(kt + 3, (kt + 3) & 3);                    \
        CP_COMMIT();                                                          \
        const uint32_t s = sb + st * GSTAGE;                                  \
        for (int ks = 0; ks < 2; ks++) {                                      \
            unsigned af[4][4], bf[4][2];                                      \
            for (int mt = 0; mt < 4; mt++)                                    \
                LDSM4(af[mt][0], af[mt][1], af[mt][2], af[mt][3], s + a_off[mt][ks]); \
            for (int np = 0; np < 2; np++)                                    \
                LDSM4(bf[np * 2][0], bf[np * 2][1], bf[np * 2 + 1][0], bf[np * 2 + 1][1], \
                      s + b_off[np][ks]);                                     \
            for (int mt = 0; mt < 4; mt++)                                    \
                for (int nt = 0; nt < 4; nt++)                                \
                    MMA_F16(acc[mt][nt], af[mt], bf[nt]);                     \
        }                                                                     \
    }

// ---- O-projection GEMM: plain fp32 output ----
__global__ __launch_bounds__(256, 2) void gemm_h_kernel(
    const __half* __restrict__ A, const __half* __restrict__ Bt,
    float* __restrict__ C, int M, int N, int K)
{
    extern __shared__ char gsm[];
    const uint32_t sb = smem_u32(gsm);
    const int tid = threadIdx.x;
    const int lane = tid & 31, w = tid >> 5;
    const int bm = blockIdx.y * 128, bn = blockIdx.x * 128;
    const int wm = (w >> 2) * 64, wn = (w & 3) * 32;
    const int grp = lane >> 2, tig = lane & 3;

    GEMM_MAINLOOP(A, Bt, K)

#pragma unroll
    for (int nt = 0; nt < 4; nt++) {
        int c = bn + wn + nt * 8 + tig * 2;
#pragma unroll
        for (int mt = 0; mt < 4; mt++) {
            int r = bm + wm + mt * 16 + grp;
            *(float2*)&C[(size_t)r * N + c]       = make_float2(acc[mt][nt][0], acc[mt][nt][1]);
            *(float2*)&C[(size_t)(r + 8) * N + c] = make_float2(acc[mt][nt][2], acc[mt][nt][3]);
        }
    }
}

// ---- QKV GEMM with fused bias + RoPE + per-head half scatter ----
// blockIdx.x = head index (N-tile == one head): 0-15 Q (rope+scale),
// 16-17 K (rope), 18-19 V (copy).
__global__ __launch_bounds__(256, 2) void gemm_qkv_kernel(
    const __half* __restrict__ A, const __half* __restrict__ Bt,
    const float* __restrict__ bias, const int* __restrict__ positions)
{
    extern __shared__ char gsm[];
    const uint32_t sb = smem_u32(gsm);
    const int tid = threadIdx.x;
    const int lane = tid & 31, w = tid >> 5;
    const int bm = blockIdx.y * 128, bn = blockIdx.x * 128;
    const int wm = (w >> 2) * 64, wn = (w & 3) * 32;
    const int grp = lane >> 2, tig = lane & 3;

    GEMM_MAINLOOP(A, Bt, HID_D)

    // ---- stage fp32 tile (+bias) in smem, pitch 132 ----
    asm volatile("cp.async.wait_group 0;" ::: "memory");
    __syncthreads();
    float* fsm = (float*)gsm;
#pragma unroll
    for (int nt = 0; nt < 4; nt++) {
        int c = wn + nt * 8 + tig * 2;
        float b0 = bias[bn + c], b1 = bias[bn + c + 1];
#pragma unroll
        for (int mt = 0; mt < 4; mt++) {
            int r = wm + mt * 16 + grp;
            *(float2*)&fsm[r * 132 + c]       = make_float2(acc[mt][nt][0] + b0, acc[mt][nt][1] + b1);
            *(float2*)&fsm[(r + 8) * 132 + c] = make_float2(acc[mt][nt][2] + b0, acc[mt][nt][3] + b1);
        }
    }
    __syncthreads();

    // ---- rope + convert + scatter: thread -> row tid>>1, half-range (tid&1)*32 ----
    const int hidx = blockIdx.x;
    const int r = tid >> 1, i0 = (tid & 1) * 32;
    const int t = bm + r, bb = t / S_LEN, ss = t % S_LEN;

    if (hidx < NH + NKV) {
        const int pos = positions[t];
        __half* out = (hidx < NH)
            ? g_qh + ((size_t)(bb * NH + hidx) * S_LEN + ss) * HD
            : g_kh + ((size_t)(bb * NKV + (hidx - NH)) * S_LEN + ss) * HD;
        const float sc = (hidx < NH) ? SCALE : 1.0f;
#pragma unroll 4
        for (int i = i0; i < i0 + 32; i += 2) {
            float2 cs = *(float2*)&g_cs[pos * HD + i];
            float2 sn = *(float2*)&g_cs[pos * HD + 64 + i];
            float2 x1 = *(float2*)&fsm[r * 132 + i];
            float2 x2 = *(float2*)&fsm[r * 132 + 64 + i];
            __half2 h1 = __floats2half2_rn((x1.x * cs.x - x2.x * sn.x) * sc,
                                           (x1.y * cs.y - x2.y * sn.y) * sc);
            __half2 h2 = __floats2half2_rn((x2.x * cs.x + x1.x * sn.x) * sc,
                                           (x2.y * cs.y + x1.y * sn.y) * sc);
            *(unsigned*)&out[i]      = *(unsigned*)&h1;
            *(unsigned*)&out[i + 64] = *(unsigned*)&h2;
        }
    } else {
        __half* out = g_vh + ((size_t)(bb * NKV + (hidx - NH - NKV)) * S_LEN + ss) * HD;
#pragma unroll 4
        for (int i = i0; i < i0 + 32; i += 2) {
            float2 x1 = *(float2*)&fsm[r * 132 + i];
            float2 x2 = *(float2*)&fsm[r * 132 + 64 + i];
            __half2 h1 = __floats2half2_rn(x1.x, x1.y);
            __half2 h2 = __floats2half2_rn(x2.x, x2.y);
            *(unsigned*)&out[i]      = *(unsigned*)&h1;
            *(unsigned*)&out[i + 64] = *(unsigned*)&h2;
        }
    }
}

// ============ Tensor-core flash attention: BQ=128, BK=64, 8 warps ============
// smem: Q 32KB @0 | stage0: K@32768 V@49152 | stage1: K@65536 V@81920  (96KB)
// Row = 128 halfs = 256B = 16 chunks of 16B; chunk c of row r at (c ^ (r&7)).
// Q is pre-scaled by SCALE (folded at rope).
#define FSMEM 98304

__global__ __launch_bounds__(256) void flash_mma_kernel()
{
    extern __shared__ char fsm[];
    const uint32_t sb = smem_u32(fsm);
    const int tid = threadIdx.x, lane = tid & 31, w = tid >> 5;
    const int grp = lane >> 2, tig = lane & 3;
    const int qb = blockIdx.x, bh = blockIdx.y;
    const int b = bh >> 4, h = bh & 15, kvh = h >> 3;

    const __half* qptr = g_qh + ((size_t)(b * NH + h) * S_LEN + qb * 128) * HD;
    const __half* kptr = g_kh + (size_t)(b * NKV + kvh) * S_LEN * HD;
    const __half* vptr = g_vh + (size_t)(b * NKV + kvh) * S_LEN * HD;

    // ---- prologue: async-load Q tile (128 rows, 256 threads: half row each) ----
    {
        const int fr = tid >> 1, fc0 = (tid & 1) * 8;
        const __half* src = qptr + (size_t)fr * HD + fc0 * 8;
        uint32_t dst = sb + fr * 256;
#pragma unroll
        for (int j = 0; j < 8; j++) {
            int c = fc0 + j;
            CP16(dst + ((c ^ (fr & 7)) << 4), src + j * 8);
        }
    }
    CP_COMMIT();

    // KV fill: 64 rows, 256 threads -> quarter row each (4 chunks K + 4 chunks V)
    const int kfr = tid >> 2, kfc0 = (tid & 3) * 4;
    auto fill_kv = [&](int kt, int st) {
        uint32_t kb = sb + 32768 + st * 32768;
        const __half* ks = kptr + (size_t)(kt * 64 + kfr) * HD + kfc0 * 8;
        const __half* vs = vptr + (size_t)(kt * 64 + kfr) * HD + kfc0 * 8;
        uint32_t rb = kfr * 256;
#pragma unroll
        for (int j = 0; j < 4; j++) {
            int c = kfc0 + j;
            uint32_t sw = rb + ((c ^ (kfr & 7)) << 4);
            CP16(kb + sw,         ks + j * 8);
            CP16(kb + 16384 + sw, vs + j * 8);
        }
    };
    fill_kv(0, 0);
    CP_COMMIT();

    // ---- Q fragments into registers (warp rows w*16..+15, kept whole loop) ----
    asm volatile("cp.async.wait_group 1;" ::: "memory");
    __syncthreads();
    unsigned qf[8][4];
    {
        int row = w * 16 + ((lane >> 3) & 1) * 8 + (lane & 7);
        uint32_t rb = sb + row * 256;
#pragma unroll
        for (int j = 0; j < 8; j++) {
            int chunk = 2 * j + (lane >> 4);
            LDSM4(qf[j][0], qf[j][1], qf[j][2], qf[j][3],
                  rb + ((chunk ^ (row & 7)) << 4));
        }
    }

    float o[16][4];
#pragma unroll
    for (int i = 0; i < 16; i++)
#pragma unroll
        for (int r = 0; r < 4; r++) o[i][r] = 0.0f;
    float m0 = -1e30f, m1 = -1e30f, l0 = 0.0f, l1 = 0.0f;

    const int ktmax = 2 * qb + 1;
    for (int kt = 0; kt <= ktmax; kt++) {
        asm volatile("cp.async.wait_group 0;" ::: "memory");
        __syncthreads();
        if (kt < ktmax) { fill_kv(kt + 1, (kt + 1) & 1); CP_COMMIT(); }

        const uint32_t kbase = sb + 32768 + (kt & 1) * 32768;
        const uint32_t vbase = kbase + 16384;

        // ---- S = Q @ K^T : warp rows w*16..+15, cols 0..63 (8 n-tiles) ----
        float s[8][4];
#pragma unroll
        for (int nt = 0; nt < 8; nt++) {
#pragma unroll
            for (int r = 0; r < 4; r++) s[nt][r] = 0.0f;
            int krow = nt * 8 + (lane & 7);
            uint32_t krb = kbase + krow * 256;
#pragma unroll
            for (int j2 = 0; j2 < 4; j2++) {
                unsigned kb0, kb1, kb2, kb3;
                int chunk = 4 * j2 + (lane >> 3);
                LDSM4(kb0, kb1, kb2, kb3, krb + ((chunk ^ (krow & 7)) << 4));
                unsigned bfa[2] = {kb0, kb1}, bfb[2] = {kb2, kb3};
                MMA_F16(s[nt], qf[2 * j2],     bfa);
                MMA_F16(s[nt], qf[2 * j2 + 1], bfb);
            }
        }

        // ---- online softmax (rows grp, grp+8 of warp tile; quad reduce) ----
        float mx0 = -1e30f, mx1 = -1e30f;
        const bool need_mask = (kt >= 2 * qb);
        const int rt0 = qb * 128 + w * 16 + grp;
#pragma unroll
        for (int nt = 0; nt < 8; nt++) {
            if (need_mask) {
                int ct = kt * 64 + nt * 8 + tig * 2;
                if (ct     > rt0)     s[nt][0] = -1e30f;
                if (ct + 1 > rt0)     s[nt][1] = -1e30f;
                if (ct     > rt0 + 8) s[nt][2] = -1e30f;
                if (ct + 1 > rt0 + 8) s[nt][3] = -1e30f;
            }
            mx0 = fmaxf(mx0, fmaxf(s[nt][0], s[nt][1]));
            mx1 = fmaxf(mx1, fmaxf(s[nt][2], s[nt][3]));
        }
        mx0 = fmaxf(mx0, __shfl_xor_sync(0xffffffffu, mx0, 1));
        mx0 = fmaxf(mx0, __shfl_xor_sync(0xffffffffu, mx0, 2));
        mx1 = fmaxf(mx1, __shfl_xor_sync(0xffffffffu, mx1, 1));
        mx1 = fmaxf(mx1, __shfl_xor_sync(0xffffffffu, mx1, 2));

        float mn0 = fmaxf(m0, mx0), mn1 = fmaxf(m1, mx1);
        float al0 = __expf(m0 - mn0), al1 = __expf(m1 - mn1);
        float ps0 = 0.0f, ps1 = 0.0f;
        unsigned ph[8][2];
#pragma unroll
        for (int nt = 0; nt < 8; nt++) {
            float e0 = __expf(s[nt][0] - mn0), e1 = __expf(s[nt][1] - mn0);
            float e2 = __expf(s[nt][2] - mn1), e3 = __expf(s[nt][3] - mn1);
            ps0 += e0 + e1; ps1 += e2 + e3;
            __half2 h0 = __floats2half2_rn(e0, e1);
            __half2 h1 = __floats2half2_rn(e2, e3);
            ph[nt][0] = *(unsigned*)&h0;
            ph[nt][1] = *(unsigned*)&h1;
        }
        ps0 += __shfl_xor_sync(0xffffffffu, ps0, 1);
        ps0 += __shfl_xor_sync(0xffffffffu, ps0, 2);
        ps1 += __shfl_xor_sync(0xffffffffu, ps1, 1);
        ps1 += __shfl_xor_sync(0xffffffffu, ps1, 2);
        l0 = l0 * al0 + ps0;  m0 = mn0;
        l1 = l1 * al1 + ps1;  m1 = mn1;
#pragma unroll
        for (int i = 0; i < 16; i++) {
            o[i][0] *= al0; o[i][1] *= al0;
            o[i][2] *= al1; o[i][3] *= al1;
        }

        // ---- O += P @ V  (P fragments straight from registers) ----
#pragma unroll
        for (int ks = 0; ks < 4; ks++) {
            unsigned af[4] = { ph[2 * ks][0], ph[2 * ks][1],
                               ph[2 * ks + 1][0], ph[2 * ks + 1][1] };
            int vrow = 16 * ks + (lane & 15);
            uint32_t vrb = vbase + vrow * 256;
#pragma unroll
            for (int p = 0; p < 8; p++) {
                unsigned v0, v1, v2, v3;
                int chunk = 2 * p + (lane >> 4);
                LDSM4T(v0, v1, v2, v3, vrb + ((chunk ^ (vrow & 7)) << 4));
                unsigned bfa[2] = {v0, v1}, bfb[2] = {v2, v3};
                MMA_F16(o[2 * p],     af, bfa);
                MMA_F16(o[2 * p + 1], af, bfb);
            }
        }
    }

    // ---- epilogue: normalize, write half to g_attnh ----
    {
        float inv0 = 1.0f / l0, inv1 = 1.0f / l1;
        int row0 = qb * 128 + w * 16 + grp;
        size_t t0 = (size_t)(b * S_LEN + row0) * OUT_N + h * HD;
        size_t t1 = t0 + 8 * OUT_N;
#pragma unroll
        for (int i = 0; i < 16; i++) {
            int d = i * 8 + tig * 2;
            __half2 h0 = __floats2half2_rn(o[i][0] * inv0, o[i][1] * inv0);
            __half2 h1 = __floats2half2_rn(o[i][2] * inv1, o[i][3] * inv1);
            *(unsigned*)&g_attnh[t0 + d] = *(unsigned*)&h0;
            *(unsigned*)&g_attnh[t1 + d] = *(unsigned*)&h1;
        }
    }
}

// ---------------- launch ----------------
extern "C" void kernel_launch(void* const* d_in, const int* in_sizes, int n_in,
                              void* d_out, int out_size)
{
    const int*   positions = nullptr;
    const float* hidden = nullptr;
    const float* Wqkv = nullptr;
    const float* bqkv = nullptr;
    const float* Wo = nullptr;
    for (int i = 0; i < n_in; i++) {
        switch (in_sizes[i]) {
            case NTOK:          positions = (const int*)d_in[i]; break;
            case NTOK * HID_D:  hidden = (const float*)d_in[i]; break;
            case HID_D * QKV_N: Wqkv = (const float*)d_in[i]; break;
            case QKV_N:         bqkv = (const float*)d_in[i]; break;
            case OUT_N * HID_D: Wo = (const float*)d_in[i]; break;
        }
    }

    __half* hidden_h; cudaGetSymbolAddress((void**)&hidden_h, g_hidden_h);
    __half* wqkvT_h;  cudaGetSymbolAddress((void**)&wqkvT_h,  g_wqkvT_h);
    __half* woT_h;    cudaGetSymbolAddress((void**)&woT_h,    g_woT_h);
    __half* attnh;    cudaGetSymbolAddress((void**)&attnh,    g_attnh);
    float* out = (float*)d_out;

    cudaFuncSetAttribute(gemm_qkv_kernel,
                         cudaFuncAttributeMaxDynamicSharedMemorySize, QSMEM);
    cudaFuncSetAttribute(gemm_h_kernel,
                         cudaFuncAttributeMaxDynamicSharedMemorySize, GSMEM);
    cudaFuncSetAttribute(flash_mma_kernel,
                         cudaFuncAttributeMaxDynamicSharedMemorySize, FSMEM);

    // 0. RoPE table + operand conversion
    rope_table_kernel<<<(S_LEN * 64 + 255) / 256, 256>>>();
    f2h_kernel<<<(NTOK * HID_D / 4 + 255) / 256, 256>>>(hidden, hidden_h, NTOK * HID_D / 4);
    {
        dim3 blk(32, 8);
        transpose_h_kernel<<<dim3(QKV_N / 32, HID_D / 32), blk>>>(Wqkv, wqkvT_h, HID_D, QKV_N);
        transpose_h_kernel<<<dim3(HID_D / 32, OUT_N / 32), blk>>>(Wo, woT_h, OUT_N, HID_D);
    }

    // 1. QKV projection with fused bias + RoPE + per-head scatter (half out)
    {
        dim3 grid(QKV_N / 128, NTOK / 128);
        gemm_qkv_kernel<<<grid, 256, QSMEM>>>(hidden_h, wqkvT_h, bqkv, positions);
    }

    // 2. Tensor-core flash attention (BQ=128, writes half output)
    {
        dim3 grid(S_LEN / 128, BATCH * NH);
        flash_mma_kernel<<<grid, 256, FSMEM>>>();
    }

    // 3. Output projection (fp32 out)
    {
        dim3 grid(HID_D / 128, NTOK / 128);
        gemm_h_kernel<<<grid, 256, GSMEM>>>(attnh, woT_h, out, NTOK, HID_D, OUT_N);
    }
}

// round 16
// speedup vs baseline: 1.0303x; 1.0303x over previous
#include <cuda_runtime.h>
#include <cuda_fp16.h>
#include <cstdint>
#include <math.h>

#define BATCH  2
#define S_LEN  2048
#define HID_D  2048
#define NH     16
#define NKV    2
#define HD     128
#define QKV_N  ((NH + 2*NKV) * HD)   // 2560
#define NTOK   (BATCH * S_LEN)       // 4096
#define OUT_N  (NH * HD)             // 2048
#define SCALE  0.08838834764831843f  // 128^-0.5
#define QSCALE (SCALE * 1.4426950408889634f)   // fold log2(e): softmax via exp2

// ---------------- scratch (device globals; no allocation allowed) ----------------
__device__ __align__(16) float  g_cs[(size_t)S_LEN * HD];
__device__ __align__(16) __half g_hidden_h[(size_t)NTOK * HID_D];
__device__ __align__(16) __half g_wqkvT_h[(size_t)QKV_N * HID_D];
__device__ __align__(16) __half g_woT_h[(size_t)HID_D * OUT_N];
__device__ __align__(16) __half g_attnh[(size_t)NTOK * OUT_N];
__device__ __align__(16) __half g_qh[(size_t)BATCH * NH * S_LEN * HD];   // roped, *QSCALE
__device__ __align__(16) __half g_kh[(size_t)BATCH * NKV * S_LEN * HD];  // roped K
__device__ __align__(16) __half g_vh[(size_t)BATCH * NKV * S_LEN * HD];  // V
__device__ unsigned g_jobs;                                              // flash job counter

// ---------------- common PTX helpers ----------------
__device__ __forceinline__ uint32_t smem_u32(const void* p) {
    uint32_t a;
    asm("{ .reg .u64 t; cvta.to.shared.u64 t, %1; cvt.u32.u64 %0, t; }" : "=r"(a) : "l"(p));
    return a;
}
#define CP16(d, s) \
    asm volatile("cp.async.cg.shared.global [%0], [%1], 16;" :: "r"(d), "l"(s))
#define CP_COMMIT() asm volatile("cp.async.commit_group;" ::: "memory")
#define LDSM4(r0, r1, r2, r3, a)                                              \
    asm volatile("ldmatrix.sync.aligned.m8n8.x4.shared.b16 {%0,%1,%2,%3}, [%4];" \
                 : "=r"(r0), "=r"(r1), "=r"(r2), "=r"(r3) : "r"(a))
#define LDSM4T(r0, r1, r2, r3, a)                                             \
    asm volatile("ldmatrix.sync.aligned.m8n8.x4.trans.shared.b16 {%0,%1,%2,%3}, [%4];" \
                 : "=r"(r0), "=r"(r1), "=r"(r2), "=r"(r3) : "r"(a))
#define MMA_F16(d, a, b)                                                      \
    asm volatile("mma.sync.aligned.m16n8k16.row.col.f32.f16.f16.f32 "         \
                 "{%0,%1,%2,%3}, {%4,%5,%6,%7}, {%8,%9}, {%0,%1,%2,%3};"      \
                 : "+f"(d[0]), "+f"(d[1]), "+f"(d[2]), "+f"(d[3])             \
                 : "r"(a[0]), "r"(a[1]), "r"(a[2]), "r"(a[3]),                \
                   "r"(b[0]), "r"(b[1]))

// ---------------- RoPE cos/sin table (fp64 for angle accuracy) ----------------
__global__ void rope_table_kernel() {
    int idx = blockIdx.x * blockDim.x + threadIdx.x;
    if (idx >= S_LEN * 64) return;
    int s = idx >> 6, i = idx & 63;
    double inv = pow(1000000.0, -(double)i / 64.0);
    double ang = (double)s * inv;
    g_cs[s * HD + i]      = (float)cos(ang);
    g_cs[s * HD + 64 + i] = (float)sin(ang);
}

// ---------------- fp32 -> fp16 convert ----------------
__global__ void f2h_kernel(const float* __restrict__ in, __half* __restrict__ out, int n4) {
    int i = blockIdx.x * blockDim.x + threadIdx.x;
    if (i >= n4) return;
    float4 v = ((const float4*)in)[i];
    __half2 h0 = __floats2half2_rn(v.x, v.y);
    __half2 h1 = __floats2half2_rn(v.z, v.w);
    ((uint2*)out)[i] = make_uint2(*(unsigned*)&h0, *(unsigned*)&h1);
}

// ---------------- weight transpose + convert: out_h[N][K] = in[K][N] ----------------
__global__ void transpose_h_kernel(const float* __restrict__ in, __half* __restrict__ out,
                                   int rows, int cols) {
    __shared__ float t[32][33];
    int x = blockIdx.x * 32 + threadIdx.x;
    int y = blockIdx.y * 32 + threadIdx.y;
#pragma unroll
    for (int j = 0; j < 32; j += 8)
        t[threadIdx.y + j][threadIdx.x] = in[(size_t)(y + j) * cols + x];
    __syncthreads();
    x = blockIdx.y * 32 + threadIdx.x;
    y = blockIdx.x * 32 + threadIdx.y;
#pragma unroll
    for (int j = 0; j < 32; j += 8)
        out[(size_t)(y + j) * rows + x] = __float2half(t[threadIdx.x][threadIdx.y + j]);
}

// ============ fp16 mma GEMM core (cp.async 4-stage + ldmatrix) ============
#define GSTAGE  16384
#define GSMEM   (4 * GSTAGE)
#define QSMEM   (132 * 128 * 4)      // rope-epilogue staging (>= GSMEM)

#define GEMM_MAINLOOP(A_, Bt_, K_)                                            \
    const int fr = tid >> 1;                                                  \
    const int fc0 = (tid & 1) * 2;                                            \
    const __half* Ap = (A_)  + (size_t)(bm + fr) * (K_) + fc0 * 8;            \
    const __half* Bp = (Bt_) + (size_t)(bn + fr) * (K_) + fc0 * 8;            \
    const uint32_t fsw0 = (uint32_t)(fr * 64 + (((fc0 + 0) ^ ((fr >> 1) & 3)) << 4)); \
    const uint32_t fsw1 = (uint32_t)(fr * 64 + (((fc0 + 1) ^ ((fr >> 1) & 3)) << 4)); \
    uint32_t a_off[4][2], b_off[2][2];                                        \
    {                                                                         \
        const int j = lane >> 3, lr = lane & 7;                               \
        for (int mt = 0; mt < 4; mt++)                                        \
            for (int ks = 0; ks < 2; ks++) {                                  \
                int row = wm + mt * 16 + (j & 1) * 8 + lr;                    \
                int kc  = ks * 2 + (j >> 1);                                  \
                a_off[mt][ks] = (uint32_t)(row * 64 + ((kc ^ ((row >> 1) & 3)) << 4)); \
            }                                                                 \
        for (int np = 0; np < 2; np++)                                        \
            for (int ks = 0; ks < 2; ks++) {                                  \
                int nt  = np * 2 + (j >> 1);                                  \
                int row = wn + nt * 8 + lr;                                   \
                int kc  = ks * 2 + (j & 1);                                   \
                b_off[np][ks] = (uint32_t)(8192 + row * 64 + ((kc ^ ((row >> 1) & 3)) << 4)); \
            }                                                                 \
    }                                                                         \
    float acc[4][4][4];                                                       \
    for (int mt = 0; mt < 4; mt++)                                            \
        for (int nt = 0; nt < 4; nt++)                                        \
            for (int r = 0; r < 4; r++) acc[mt][nt][r] = 0.0f;                \
    const int nk = (K_) >> 5;                                                 \
    auto load_stage = [&](int kt, int st) {                                   \
        uint32_t s = sb + st * GSTAGE;                                        \
        const __half* ap = Ap + kt * 32;                                      \
        const __half* bp = Bp + kt * 32;                                      \
        CP16(s + fsw0,        ap);                                            \
        CP16(s + fsw1,        ap + 8);                                        \
        CP16(s + 8192 + fsw0, bp);                                            \
        CP16(s + 8192 + fsw1, bp + 8);                                        \
    };                                                                        \
    for (int s = 0; s < 3; s++) { load_stage(s, s); CP_COMMIT(); }            \
    for (int kt = 0; kt < nk; kt++) {                                         \
        asm volatile("cp.async.wait_group 2;" ::: "memory");                  \
        __syncthreads();                                                      \
        const int st = kt & 3;                                                \
        if (kt + 3 < nk) load_stage(kt + 3, (kt + 3) & 3);                    \
        CP_COMMIT();                                                          \
        const uint32_t s = sb + st * GSTAGE;                                  \
        for (int ks = 0; ks < 2; ks++) {                                      \
            unsigned af[4][4], bf[4][2];                                      \
            for (int mt = 0; mt < 4; mt++)                                    \
                LDSM4(af[mt][0], af[mt][1], af[mt][2], af[mt][3], s + a_off[mt][ks]); \
            for (int np = 0; np < 2; np++)                                    \
                LDSM4(bf[np * 2][0], bf[np * 2][1], bf[np * 2 + 1][0], bf[np * 2 + 1][1], \
                      s + b_off[np][ks]);                                     \
            for (int mt = 0; mt < 4; mt++)                                    \
                for (int nt = 0; nt < 4; nt++)                                \
                    MMA_F16(acc[mt][nt], af[mt], bf[nt]);                     \
        }                                                                     \
    }

// ---- O-projection GEMM: plain fp32 output ----
__global__ __launch_bounds__(256, 2) void gemm_h_kernel(
    const __half* __restrict__ A, const __half* __restrict__ Bt,
    float* __restrict__ C, int M, int N, int K)
{
    extern __shared__ char gsm[];
    const uint32_t sb = smem_u32(gsm);
    const int tid = threadIdx.x;
    const int lane = tid & 31, w = tid >> 5;
    const int bm = blockIdx.y * 128, bn = blockIdx.x * 128;
    const int wm = (w >> 2) * 64, wn = (w & 3) * 32;
    const int grp = lane >> 2, tig = lane & 3;

    GEMM_MAINLOOP(A, Bt, K)

#pragma unroll
    for (int nt = 0; nt < 4; nt++) {
        int c = bn + wn + nt * 8 + tig * 2;
#pragma unroll
        for (int mt = 0; mt < 4; mt++) {
            int r = bm + wm + mt * 16 + grp;
            *(float2*)&C[(size_t)r * N + c]       = make_float2(acc[mt][nt][0], acc[mt][nt][1]);
            *(float2*)&C[(size_t)(r + 8) * N + c] = make_float2(acc[mt][nt][2], acc[mt][nt][3]);
        }
    }
}

// ---- QKV GEMM with fused bias + RoPE + per-head half scatter ----
// blockIdx.x = head index: 0-15 Q (rope, *QSCALE), 16-17 K (rope), 18-19 V (copy).
__global__ __launch_bounds__(256, 2) void gemm_qkv_kernel(
    const __half* __restrict__ A, const __half* __restrict__ Bt,
    const float* __restrict__ bias, const int* __restrict__ positions)
{
    extern __shared__ char gsm[];
    const uint32_t sb = smem_u32(gsm);
    const int tid = threadIdx.x;
    const int lane = tid & 31, w = tid >> 5;
    const int bm = blockIdx.y * 128, bn = blockIdx.x * 128;
    const int wm = (w >> 2) * 64, wn = (w & 3) * 32;
    const int grp = lane >> 2, tig = lane & 3;

    GEMM_MAINLOOP(A, Bt, HID_D)

    asm volatile("cp.async.wait_group 0;" ::: "memory");
    __syncthreads();
    float* fsm = (float*)gsm;
#pragma unroll
    for (int nt = 0; nt < 4; nt++) {
        int c = wn + nt * 8 + tig * 2;
        float b0 = bias[bn + c], b1 = bias[bn + c + 1];
#pragma unroll
        for (int mt = 0; mt < 4; mt++) {
            int r = wm + mt * 16 + grp;
            *(float2*)&fsm[r * 132 + c]       = make_float2(acc[mt][nt][0] + b0, acc[mt][nt][1] + b1);
            *(float2*)&fsm[(r + 8) * 132 + c] = make_float2(acc[mt][nt][2] + b0, acc[mt][nt][3] + b1);
        }
    }
    __syncthreads();

    const int hidx = blockIdx.x;
    const int r = tid >> 1, i0 = (tid & 1) * 32;
    const int t = bm + r, bb = t / S_LEN, ss = t % S_LEN;

    if (hidx < NH + NKV) {
        const int pos = positions[t];
        __half* out = (hidx < NH)
            ? g_qh + ((size_t)(bb * NH + hidx) * S_LEN + ss) * HD
            : g_kh + ((size_t)(bb * NKV + (hidx - NH)) * S_LEN + ss) * HD;
        const float sc = (hidx < NH) ? QSCALE : 1.0f;
#pragma unroll 4
        for (int i = i0; i < i0 + 32; i += 2) {
            float2 cs = *(float2*)&g_cs[pos * HD + i];
            float2 sn = *(float2*)&g_cs[pos * HD + 64 + i];
            float2 x1 = *(float2*)&fsm[r * 132 + i];
            float2 x2 = *(float2*)&fsm[r * 132 + 64 + i];
            __half2 h1 = __floats2half2_rn((x1.x * cs.x - x2.x * sn.x) * sc,
                                           (x1.y * cs.y - x2.y * sn.y) * sc);
            __half2 h2 = __floats2half2_rn((x2.x * cs.x + x1.x * sn.x) * sc,
                                           (x2.y * cs.y + x1.y * sn.y) * sc);
            *(unsigned*)&out[i]      = *(unsigned*)&h1;
            *(unsigned*)&out[i + 64] = *(unsigned*)&h2;
        }
    } else {
        __half* out = g_vh + ((size_t)(bb * NKV + (hidx - NH - NKV)) * S_LEN + ss) * HD;
#pragma unroll 4
        for (int i = i0; i < i0 + 32; i += 2) {
            float2 x1 = *(float2*)&fsm[r * 132 + i];
            float2 x2 = *(float2*)&fsm[r * 132 + 64 + i];
            __half2 h1 = __floats2half2_rn(x1.x, x1.y);
            __half2 h2 = __floats2half2_rn(x2.x, x2.y);
            *(unsigned*)&out[i]      = *(unsigned*)&h1;
            *(unsigned*)&out[i + 64] = *(unsigned*)&h2;
        }
    }
}

// ============ Persistent LPT tensor-core flash attention: BQ=128, BK=64 ============
// Jobs pulled in DESCENDING work order: job j -> qb = 15 - j/32 (heaviest first),
// bh = j%32. 512 jobs total. Q pre-scaled by SCALE*log2e -> softmax via exp2f.
// smem: Q 32KB @0 | stage0: K@32768 V@49152 | stage1: K@65536 V@81920  (96KB)
#define FSMEM 98304
#define NJOBS 512

__global__ __launch_bounds__(256) void flash_mma_kernel()
{
    extern __shared__ char fsm[];
    const uint32_t sb = smem_u32(fsm);
    const int tid = threadIdx.x, lane = tid & 31, w = tid >> 5;
    const int grp = lane >> 2, tig = lane & 3;
    __shared__ unsigned s_job;

    for (;;) {
        if (tid == 0) s_job = atomicAdd(&g_jobs, 1u);
        __syncthreads();
        const unsigned j = s_job;
        if (j >= NJOBS) return;
        const int qb = 15 - (int)(j >> 5);
        const int bh = (int)(j & 31);
        const int b = bh >> 4, h = bh & 15, kvh = h >> 3;

        const __half* qptr = g_qh + ((size_t)(b * NH + h) * S_LEN + qb * 128) * HD;
        const __half* kptr = g_kh + (size_t)(b * NKV + kvh) * S_LEN * HD;
        const __half* vptr = g_vh + (size_t)(b * NKV + kvh) * S_LEN * HD;

        // ---- prologue: async-load Q tile (128 rows, half row per thread) ----
        {
            const int fr = tid >> 1, fc0 = (tid & 1) * 8;
            const __half* src = qptr + (size_t)fr * HD + fc0 * 8;
            uint32_t dst = sb + fr * 256;
#pragma unroll
            for (int jj = 0; jj < 8; jj++) {
                int c = fc0 + jj;
                CP16(dst + ((c ^ (fr & 7)) << 4), src + jj * 8);
            }
        }
        CP_COMMIT();

        const int kfr = tid >> 2, kfc0 = (tid & 3) * 4;
        auto fill_kv = [&](int kt, int st) {
            uint32_t kb = sb + 32768 + st * 32768;
            const __half* ks = kptr + (size_t)(kt * 64 + kfr) * HD + kfc0 * 8;
            const __half* vs = vptr + (size_t)(kt * 64 + kfr) * HD + kfc0 * 8;
            uint32_t rb = kfr * 256;
#pragma unroll
            for (int jj = 0; jj < 4; jj++) {
                int c = kfc0 + jj;
                uint32_t sw = rb + ((c ^ (kfr & 7)) << 4);
                CP16(kb + sw,         ks + jj * 8);
                CP16(kb + 16384 + sw, vs + jj * 8);
            }
        };
        fill_kv(0, 0);
        CP_COMMIT();

        // ---- Q fragments into registers ----
        asm volatile("cp.async.wait_group 1;" ::: "memory");
        __syncthreads();
        unsigned qf[8][4];
        {
            int row = w * 16 + ((lane >> 3) & 1) * 8 + (lane & 7);
            uint32_t rb = sb + row * 256;
#pragma unroll
            for (int jj = 0; jj < 8; jj++) {
                int chunk = 2 * jj + (lane >> 4);
                LDSM4(qf[jj][0], qf[jj][1], qf[jj][2], qf[jj][3],
                      rb + ((chunk ^ (row & 7)) << 4));
            }
        }

        float o[16][4];
#pragma unroll
        for (int i = 0; i < 16; i++)
#pragma unroll
            for (int r = 0; r < 4; r++) o[i][r] = 0.0f;
        float m0 = -1e30f, m1 = -1e30f, l0 = 0.0f, l1 = 0.0f;

        const int ktmax = 2 * qb + 1;
        for (int kt = 0; kt <= ktmax; kt++) {
            asm volatile("cp.async.wait_group 0;" ::: "memory");
            __syncthreads();
            if (kt < ktmax) { fill_kv(kt + 1, (kt + 1) & 1); CP_COMMIT(); }

            const uint32_t kbase = sb + 32768 + (kt & 1) * 32768;
            const uint32_t vbase = kbase + 16384;

            // ---- S = Q @ K^T ----
            float s[8][4];
#pragma unroll
            for (int nt = 0; nt < 8; nt++) {
#pragma unroll
                for (int r = 0; r < 4; r++) s[nt][r] = 0.0f;
                int krow = nt * 8 + (lane & 7);
                uint32_t krb = kbase + krow * 256;
#pragma unroll
                for (int j2 = 0; j2 < 4; j2++) {
                    unsigned kb0, kb1, kb2, kb3;
                    int chunk = 4 * j2 + (lane >> 3);
                    LDSM4(kb0, kb1, kb2, kb3, krb + ((chunk ^ (krow & 7)) << 4));
                    unsigned bfa[2] = {kb0, kb1}, bfb[2] = {kb2, kb3};
                    MMA_F16(s[nt], qf[2 * j2],     bfa);
                    MMA_F16(s[nt], qf[2 * j2 + 1], bfb);
                }
            }

            // ---- online softmax in log2 domain (exp2f) ----
            float mx0 = -1e30f, mx1 = -1e30f;
            const bool need_mask = (kt >= 2 * qb);
            const int rt0 = qb * 128 + w * 16 + grp;
#pragma unroll
            for (int nt = 0; nt < 8; nt++) {
                if (need_mask) {
                    int ct = kt * 64 + nt * 8 + tig * 2;
                    if (ct     > rt0)     s[nt][0] = -1e30f;
                    if (ct + 1 > rt0)     s[nt][1] = -1e30f;
                    if (ct     > rt0 + 8) s[nt][2] = -1e30f;
                    if (ct + 1 > rt0 + 8) s[nt][3] = -1e30f;
                }
                mx0 = fmaxf(mx0, fmaxf(s[nt][0], s[nt][1]));
                mx1 = fmaxf(mx1, fmaxf(s[nt][2], s[nt][3]));
            }
            mx0 = fmaxf(mx0, __shfl_xor_sync(0xffffffffu, mx0, 1));
            mx0 = fmaxf(mx0, __shfl_xor_sync(0xffffffffu, mx0, 2));
            mx1 = fmaxf(mx1, __shfl_xor_sync(0xffffffffu, mx1, 1));
            mx1 = fmaxf(mx1, __shfl_xor_sync(0xffffffffu, mx1, 2));

            float mn0 = fmaxf(m0, mx0), mn1 = fmaxf(m1, mx1);
            float al0 = exp2f(m0 - mn0), al1 = exp2f(m1 - mn1);
            float ps0 = 0.0f, ps1 = 0.0f;
            unsigned ph[8][2];
#pragma unroll
            for (int nt = 0; nt < 8; nt++) {
                float e0 = exp2f(s[nt][0] - mn0), e1 = exp2f(s[nt][1] - mn0);
                float e2 = exp2f(s[nt][2] - mn1), e3 = exp2f(s[nt][3] - mn1);
                ps0 += e0 + e1; ps1 += e2 + e3;
                __half2 h0 = __floats2half2_rn(e0, e1);
                __half2 h1 = __floats2half2_rn(e2, e3);
                ph[nt][0] = *(unsigned*)&h0;
                ph[nt][1] = *(unsigned*)&h1;
            }
            ps0 += __shfl_xor_sync(0xffffffffu, ps0, 1);
            ps0 += __shfl_xor_sync(0xffffffffu, ps0, 2);
            ps1 += __shfl_xor_sync(0xffffffffu, ps1, 1);
            ps1 += __shfl_xor_sync(0xffffffffu, ps1, 2);
            l0 = l0 * al0 + ps0;  m0 = mn0;
            l1 = l1 * al1 + ps1;  m1 = mn1;
#pragma unroll
            for (int i = 0; i < 16; i++) {
                o[i][0] *= al0; o[i][1] *= al0;
                o[i][2] *= al1; o[i][3] *= al1;
            }

            // ---- O += P @ V ----
#pragma unroll
            for (int ks = 0; ks < 4; ks++) {
                unsigned af[4] = { ph[2 * ks][0], ph[2 * ks][1],
                                   ph[2 * ks + 1][0], ph[2 * ks + 1][1] };
                int vrow = 16 * ks + (lane & 15);
                uint32_t vrb = vbase + vrow * 256;
#pragma unroll
                for (int p = 0; p < 8; p++) {
                    unsigned v0, v1, v2, v3;
                    int chunk = 2 * p + (lane >> 4);
                    LDSM4T(v0, v1, v2, v3, vrb + ((chunk ^ (vrow & 7)) << 4));
                    unsigned bfa[2] = {v0, v1}, bfb[2] = {v2, v3};
                    MMA_F16(o[2 * p],     af, bfa);
                    MMA_F16(o[2 * p + 1], af, bfb);
                }
            }
        }

        // ---- epilogue: normalize, write half to g_attnh ----
        {
            float inv0 = 1.0f / l0, inv1 = 1.0f / l1;
            int row0 = qb * 128 + w * 16 + grp;
            size_t t0 = (size_t)(b * S_LEN + row0) * OUT_N + h * HD;
            size_t t1 = t0 + 8 * OUT_N;
#pragma unroll
            for (int i = 0; i < 16; i++) {
                int d = i * 8 + tig * 2;
                __half2 h0 = __floats2half2_rn(o[i][0] * inv0, o[i][1] * inv0);
                __half2 h1 = __floats2half2_rn(o[i][2] * inv1, o[i][3] * inv1);
                *(unsigned*)&g_attnh[t0 + d] = *(unsigned*)&h0;
                *(unsigned*)&g_attnh[t1 + d] = *(unsigned*)&h1;
            }
        }
        __syncthreads();   // smem safe to reuse for next job
    }
}

// ---------------- launch ----------------
extern "C" void kernel_launch(void* const* d_in, const int* in_sizes, int n_in,
                              void* d_out, int out_size)
{
    const int*   positions = nullptr;
    const float* hidden = nullptr;
    const float* Wqkv = nullptr;
    const float* bqkv = nullptr;
    const float* Wo = nullptr;
    for (int i = 0; i < n_in; i++) {
        switch (in_sizes[i]) {
            case NTOK:          positions = (const int*)d_in[i]; break;
            case NTOK * HID_D:  hidden = (const float*)d_in[i]; break;
            case HID_D * QKV_N: Wqkv = (const float*)d_in[i]; break;
            case QKV_N:         bqkv = (const float*)d_in[i]; break;
            case OUT_N * HID_D: Wo = (const float*)d_in[i]; break;
        }
    }

    __half* hidden_h; cudaGetSymbolAddress((void**)&hidden_h, g_hidden_h);
    __half* wqkvT_h;  cudaGetSymbolAddress((void**)&wqkvT_h,  g_wqkvT_h);
    __half* woT_h;    cudaGetSymbolAddress((void**)&woT_h,    g_woT_h);
    __half* attnh;    cudaGetSymbolAddress((void**)&attnh,    g_attnh);
    void* jobs_ptr;   cudaGetSymbolAddress(&jobs_ptr, g_jobs);
    float* out = (float*)d_out;

    cudaFuncSetAttribute(gemm_qkv_kernel,
                         cudaFuncAttributeMaxDynamicSharedMemorySize, QSMEM);
    cudaFuncSetAttribute(gemm_h_kernel,
                         cudaFuncAttributeMaxDynamicSharedMemorySize, GSMEM);
    cudaFuncSetAttribute(flash_mma_kernel,
                         cudaFuncAttributeMaxDynamicSharedMemorySize, FSMEM);

    // 0. RoPE table + operand conversion + job counter reset
    cudaMemsetAsync(jobs_ptr, 0, sizeof(unsigned));
    rope_table_kernel<<<(S_LEN * 64 + 255) / 256, 256>>>();
    f2h_kernel<<<(NTOK * HID_D / 4 + 255) / 256, 256>>>(hidden, hidden_h, NTOK * HID_D / 4);
    {
        dim3 blk(32, 8);
        transpose_h_kernel<<<dim3(QKV_N / 32, HID_D / 32), blk>>>(Wqkv, wqkvT_h, HID_D, QKV_N);
        transpose_h_kernel<<<dim3(HID_D / 32, OUT_N / 32), blk>>>(Wo, woT_h, OUT_N, HID_D);
    }

    // 1. QKV projection with fused bias + RoPE + per-head scatter (half out)
    {
        dim3 grid(QKV_N / 128, NTOK / 128);
        gemm_qkv_kernel<<<grid, 256, QSMEM>>>(hidden_h, wqkvT_h, bqkv, positions);
    }

    // 2. Persistent LPT flash attention (BQ=128, exp2 softmax, half out)
    flash_mma_kernel<<<296, 256, FSMEM>>>();

    // 3. Output projection (fp32 out)
    {
        dim3 grid(HID_D / 128, NTOK / 128);
        gemm_h_kernel<<<grid, 256, GSMEM>>>(attnh, woT_h, out, NTOK, HID_D, OUT_N);
    }
}